// round 15
// baseline (speedup 1.0000x reference)
#include <cuda_runtime.h>
#include <cuda_fp16.h>
#include <math.h>
#include <stdint.h>

// ---------------------------------------------------------------------------
// PE_GatedBlock: B=8192, N0=128, N1=64, NS=128, NV=64
//   scalars = [sym-pair feats x0 | sym-dot feats x1] @ WSC   (mma.sync fp16)
//              N-split grid (128,2) -> 2 CTAs/SM
//   Zt = (1/128) x0 @ w011  (transposed [b][w*64+v], fp16)
//   v111 = cross feats @ WVA (mma.sync fp16), M-split grid 256 -> 2+ CTAs/SM
//   v011 from Zt contraction (fp32 epilogue, contiguous fp16 reads), gating fused.
//   out = [silu(s[:,:128]) | (v111+v011)*sigmoid(s[:,128:])]
// Precision: fp16 operands, fp32 accumulate (measured rel_err ~3.3e-4 vs 1e-3).
// NOTE: harness ptxas targets sm_103 (no 'a') -> tcgen05 unavailable; mma.sync.
// ---------------------------------------------------------------------------

#define BATCH   8192
#define XDIM    320
#define NN0     128
#define NN1     64
#define NSV     192
#define NVD     64

#define NP0     8256
#define NP1     2080
#define NPA     2016
#define NPA_PAD 2048
#define NCHV    32
#define KSC     (NP0 + NP1)          // 10336
#define KSC_PAD 10368                // 162*64 ; NP0 = 129*64 exactly
#define NCHUNK  162
#define NCH0    129

// ---- static device scratch -------------------------------------------------
__device__ __align__(16) __half g_WSC[KSC_PAD * NSV];    // [k][n]
__device__ __align__(16) __half g_W3[NN0 * NN1 * NVD];   // [u][w*64+v]
__device__ __align__(16) __half g_WVA[NPA_PAD * NVD];    // [p][w]
__device__ __align__(4) unsigned short g_sp[KSC_PAD];
__device__ __align__(4) unsigned short g_pa[NPA_PAD];
__device__ __align__(16) __half g_Zh[(size_t)BATCH * NN1 * NVD];  // [b][w*64+v]
__device__ float g_G[BATCH * NVD];

// ---- triangular index helpers ----------------------------------------------
__device__ __forceinline__ void tri_le(int p, int& u, int& v) {
    int vv = (int)floorf((sqrtf(8.0f * (float)p + 1.0f) - 1.0f) * 0.5f);
    while ((vv + 1) * (vv + 2) / 2 <= p) vv++;
    while (vv * (vv + 1) / 2 > p) vv--;
    v = vv;
    u = p - vv * (vv + 1) / 2;
}
__device__ __forceinline__ void tri_lt(int p, int& u, int& v) {
    int vv = (int)floorf((1.0f + sqrtf(8.0f * (float)p + 1.0f)) * 0.5f);
    while ((vv + 1) * vv / 2 <= p) vv++;
    while (vv * (vv - 1) / 2 > p) vv--;
    v = vv;
    u = p - vv * (vv - 1) / 2;
}

__device__ __forceinline__ uint32_t pack_f16x2(float f0, float f1) {
    __half2 h2 = __floats2half2_rn(f0, f1);
    return *(uint32_t*)&h2;
}
__device__ __forceinline__ float2 h2f(uint32_t u) {
    __half2 h = *(__half2*)&u;
    return __half22float2(h);
}

// ---- pair lists ---------------------------------------------------------------
__global__ void build_pairs() {
    int p = blockIdx.x * blockDim.x + threadIdx.x;
    if (p < KSC_PAD) {
        unsigned short pk = 0;
        if (p < NP0) {
            int u, v; tri_le(p, u, v);
            pk = (unsigned short)((u << 8) | v);
        } else if (p < KSC) {
            int u, v; tri_le(p - NP0, u, v);
            pk = (unsigned short)((u << 8) | v);
        }
        g_sp[p] = pk;
    }
    if (p < NPA_PAD) {
        unsigned short pk = 0;
        if (p < NPA) {
            int u, v; tri_lt(p, u, v);
            pk = (unsigned short)((u << 8) | v);
        }
        g_pa[p] = pk;
    }
}

// ---- weight folding -------------------------------------------------------------
__global__ void build_wsc(const float* __restrict__ w000,
                          const float* __restrict__ w110) {
    int p = blockIdx.x;
    int w = threadIdx.x;
    const float inv_sqrt2 = 0.7071067811865476f;
    float f = 0.0f;
    unsigned int pk = g_sp[p];
    int u = pk >> 8, v = pk & 255;
    if (p < NP0) {
        float val = w000[(u * NN0 + v) * NSV + w];
        if (u != v) val += w000[(v * NN0 + u) * NSV + w];
        f = (inv_sqrt2 / 128.0f) * val;
    } else if (p < KSC) {
        float val = w110[(u * NN1 + v) * NSV + w];
        if (u != v) val += w110[(v * NN1 + u) * NSV + w];
        f = (inv_sqrt2 / (64.0f * 1.7320508075688772f)) * val;
    }
    g_WSC[p * NSV + w] = __float2half_rn(f);
}

__global__ void build_wva(const float* __restrict__ w111) {
    int p = blockIdx.x;
    int w = threadIdx.x;
    float f = 0.0f;
    unsigned int pk = g_pa[p];
    int u = pk >> 8, v = pk & 255;
    if (p < NPA) {
        f = (1.0f / 128.0f) *
            (w111[(u * NN1 + v) * NVD + w] - w111[(v * NN1 + u) * NVD + w]);
    }
    g_WVA[p * NVD + w] = __float2half_rn(f);
}

// w011[u][v][w] -> g_W3[u][w*64+v] via smem transpose, 1024 threads
__global__ void build_w3(const float* __restrict__ w011) {
    __shared__ float tile[64][65];
    int u = blockIdx.x;
    const float* src = w011 + (size_t)u * 4096;
    for (int i = threadIdx.x; i < 4096; i += 1024) {
        int v = i >> 6, w = i & 63;
        tile[v][w] = src[i];
    }
    __syncthreads();
    __half* dst = g_W3 + (size_t)u * 4096;
    for (int i = threadIdx.x; i < 4096; i += 1024) {
        int w = i >> 6, v = i & 63;
        dst[i] = __float2half_rn(tile[v][w] * (1.0f / 128.0f));
    }
}

// ---- mma.sync helpers --------------------------------------------------------
__device__ __forceinline__ void mma_f16(float* d, const uint32_t* a, const uint32_t* b) {
    asm volatile(
        "mma.sync.aligned.m16n8k16.row.col.f32.f16.f16.f32 "
        "{%0,%1,%2,%3}, {%4,%5,%6,%7}, {%8,%9}, {%0,%1,%2,%3};\n"
        : "+f"(d[0]), "+f"(d[1]), "+f"(d[2]), "+f"(d[3])
        : "r"(a[0]), "r"(a[1]), "r"(a[2]), "r"(a[3]), "r"(b[0]), "r"(b[1]));
}
__device__ __forceinline__ void ldsm_x4(uint32_t* r, uint32_t addr) {
    asm volatile("ldmatrix.sync.aligned.m8n8.x4.shared.b16 {%0,%1,%2,%3}, [%4];"
                 : "=r"(r[0]), "=r"(r[1]), "=r"(r[2]), "=r"(r[3]) : "r"(addr));
}
__device__ __forceinline__ void ldsm_x2t(uint32_t* r, uint32_t addr) {
    asm volatile("ldmatrix.sync.aligned.m8n8.x2.trans.shared.b16 {%0,%1}, [%2];"
                 : "=r"(r[0]), "=r"(r[1]) : "r"(addr));
}
__device__ __forceinline__ void cp16(uint32_t dst, const void* src) {
    asm volatile("cp.async.cg.shared.global [%0], [%1], 16;"
                 :: "r"(dst), "l"(src) : "memory");
}

// ---- g3 on tensor cores: g_Zh = x0[8192x128] @ W3[128x4096] (fp16 out) -------
#define G3_AS  136
#define G3_BS  136
#define G3_A   0
#define G3_B   17408
#define G3T_SMEM 52224

__global__ void __launch_bounds__(256) g3_tc(const float* __restrict__ x) {
    extern __shared__ char g3m[];
    const int t = threadIdx.x;
    const int lane = t & 31, warp = t >> 5;
    const int wm = warp & 1, wn = warp >> 1;
    const int row0 = blockIdx.x * 64;
    const int col0 = blockIdx.y * 128;

    uint32_t sb;
    asm("{ .reg .u64 u; cvta.to.shared.u64 u, %1; cvt.u32.u64 %0, u; }"
        : "=r"(sb) : "l"(g3m));

#pragma unroll
    for (int j = 0; j < 8; j++) {
        int i = t + j * 256;
        int r = i >> 4, cc = (i & 15) * 8;
        uint32_t doff = (uint32_t)(r * (G3_BS * 2) + cc * 2);
        cp16(sb + G3_B + doff, g_W3 + (size_t)r * 4096 + col0 + cc);
    }
    asm volatile("cp.async.commit_group;" ::: "memory");

    for (int i = t; i < 4096; i += 256) {
        int r = i >> 6, c2 = (i & 63) * 2;
        const float* xp = x + (size_t)(row0 + r) * XDIM + c2;
        *(uint32_t*)(g3m + G3_A + r * (G3_AS * 2) + c2 * 2) = pack_f16x2(xp[0], xp[1]);
    }
    asm volatile("cp.async.wait_group 0;" ::: "memory");
    __syncthreads();

    float acc[2][4][4];
#pragma unroll
    for (int mt = 0; mt < 2; mt++)
#pragma unroll
        for (int nt = 0; nt < 4; nt++)
#pragma unroll
            for (int q = 0; q < 4; q++) acc[mt][nt][q] = 0.0f;

    const uint32_t a_eoff = (uint32_t)((wm * 32 + (lane & 15)) * G3_AS +
                                       (lane >> 4) * 8) * 2;
    const uint32_t b_eoff = (uint32_t)((lane & 15) * G3_BS + wn * 32) * 2;

#pragma unroll
    for (int ks = 0; ks < 8; ks++) {
        uint32_t a[2][4];
#pragma unroll
        for (int mt = 0; mt < 2; mt++) {
            uint32_t eo = a_eoff + (uint32_t)(mt * 16 * G3_AS + ks * 16) * 2;
            ldsm_x4(a[mt], sb + G3_A + eo);
        }
        uint32_t b[4][2];
#pragma unroll
        for (int nt = 0; nt < 4; nt++) {
            uint32_t eo = b_eoff + (uint32_t)(ks * 16 * G3_BS + nt * 8) * 2;
            ldsm_x2t(b[nt], sb + G3_B + eo);
        }
#pragma unroll
        for (int mt = 0; mt < 2; mt++)
#pragma unroll
            for (int nt = 0; nt < 4; nt++)
                mma_f16(acc[mt][nt], a[mt], b[nt]);
    }

#pragma unroll
    for (int mt = 0; mt < 2; mt++)
#pragma unroll
        for (int nt = 0; nt < 4; nt++) {
            int r = row0 + wm * 32 + mt * 16 + (lane >> 2);
            int c = col0 + wn * 32 + nt * 8 + (lane & 3) * 2;
            *(uint32_t*)&g_Zh[(size_t)r * 4096 + c] =
                pack_f16x2(acc[mt][nt][0], acc[mt][nt][1]);
            *(uint32_t*)&g_Zh[(size_t)(r + 8) * 4096 + c] =
                pack_f16x2(acc[mt][nt][2], acc[mt][nt][3]);
        }
}

// ---- scalars: N-split pipelined mma.sync, grid (128,2), 512 threads ------------
// per CTA: C[64 x 96]; warp grid 4(M) x 4(N), warp tile 16 x 24.
#define AS_STRIDE 72      // fp16; 144B rows (16 mod 128) conflict-free
#define BS_STRIDE 104     // fp16; 208B rows (80 mod 128, odd*16) conflict-free

#define SM_XS   0                           // 64x196 f32 max
#define SM_A0   50176
#define SM_A1   59392
#define SM_B0   68608                       // 64*104*2 = 13312 per stage
#define SM_B1   81920
#define TC_SMEM 95232

__global__ void __launch_bounds__(512) scalars_tc14(const float* __restrict__ x,
                                                    float* __restrict__ out) {
    extern __shared__ char tcsm[];
    float* Xs = (float*)(tcsm + SM_XS);
    const int t = threadIdx.x;
    const int lane = t & 31, warp = t >> 5;
    const int wm = warp & 3, wn = warp >> 2;       // 4 x 4
    const int row0 = blockIdx.x * 64;
    const int n0 = blockIdx.y * 96;

    uint32_t sb;
    asm("{ .reg .u64 u; cvta.to.shared.u64 u, %1; cvt.u32.u64 %0, u; }"
        : "=r"(sb) : "l"(tcsm));

    const uint32_t AA[2] = {sb + SM_A0, sb + SM_A1};
    const uint32_t BB[2] = {sb + SM_B0, sb + SM_B1};

    for (int i = t; i < 64 * 32; i += 512) {
        int r = i >> 5, c4 = (i & 31) << 2;
        *(float4*)&Xs[r * 132 + c4] =
            *(const float4*)&x[(size_t)(row0 + r) * XDIM + c4];
    }
    __syncthreads();

    const int kk2 = lane * 2;
    const int mg = warp * 4;

    auto build_A = [&](int c, int st) {
        char* aa = tcsm + (st ? SM_A1 : SM_A0);
        int kg = c * 64 + kk2;
        uint32_t pk = __ldg((const uint32_t*)&g_sp[kg]);
        int u0 = (pk >> 8) & 255, v0 = pk & 255;
        int u1 = pk >> 24,       v1 = (pk >> 16) & 255;
        if (c < NCH0) {
#pragma unroll
            for (int j = 0; j < 4; j++) {
                int m = mg + j;
                const float* Xr = Xs + m * 132;
                *(uint32_t*)(aa + m * (AS_STRIDE * 2) + kk2 * 2) =
                    pack_f16x2(Xr[u0] * Xr[v0], Xr[u1] * Xr[v1]);
            }
        } else {
#pragma unroll
            for (int j = 0; j < 4; j++) {
                int m = mg + j;
                const float* Xr = Xs + m * 196;
                const float* a0 = Xr + 3 * u0; const float* b0 = Xr + 3 * v0;
                const float* a1 = Xr + 3 * u1; const float* b1 = Xr + 3 * v1;
                float f0 = a0[0] * b0[0] + a0[1] * b0[1] + a0[2] * b0[2];
                float f1 = a1[0] * b1[0] + a1[1] * b1[1] + a1[2] * b1[2];
                *(uint32_t*)(aa + m * (AS_STRIDE * 2) + kk2 * 2) = pack_f16x2(f0, f1);
            }
        }
    };
    // B tile: 64 rows x 96 fp16 = 768 16B-chunks
    auto fetch_B = [&](int c, int st) {
        const uint32_t bb = BB[st];
        const int k0 = c * 64;
#pragma unroll
        for (int j = 0; j < 2; j++) {
            int i = t + j * 512;
            if (i < 768) {
                int r = i / 12, cc = (i - r * 12) * 8;
                uint32_t doff = (uint32_t)(r * (BS_STRIDE * 2) + cc * 2);
                cp16(bb + doff, g_WSC + (size_t)(k0 + r) * NSV + n0 + cc);
            }
        }
        asm volatile("cp.async.commit_group;" ::: "memory");
    };

    float acc[3][4];
#pragma unroll
    for (int nt = 0; nt < 3; nt++)
#pragma unroll
        for (int q = 0; q < 4; q++) acc[nt][q] = 0.0f;

    const uint32_t a_eoff = (uint32_t)((wm * 16 + (lane & 15)) * AS_STRIDE +
                                       (lane >> 4) * 8) * 2;
    const uint32_t b_eoff = (uint32_t)((lane & 15) * BS_STRIDE + wn * 24) * 2;

    fetch_B(0, 0);
    build_A(0, 0);
    asm volatile("cp.async.wait_group 0;" ::: "memory");
    __syncthreads();

    for (int i = 0; i < NCHUNK; i++) {
        const int s = i & 1;
        if (i + 1 < NCHUNK) {
            if (i + 1 == NCH0) {
                for (int j = t; j < 64 * 48; j += 512) {
                    int r = j / 48, c4 = (j - r * 48) << 2;
                    *(float4*)&Xs[r * 196 + c4] =
                        *(const float4*)&x[(size_t)(row0 + r) * XDIM + 128 + c4];
                }
                __syncthreads();
            }
            fetch_B(i + 1, s ^ 1);
            build_A(i + 1, s ^ 1);
        }

#pragma unroll
        for (int ks = 0; ks < 4; ks++) {
            uint32_t a[4];
            {
                uint32_t eo = a_eoff + (uint32_t)(ks * 16) * 2;
                ldsm_x4(a, AA[s] + eo);
            }
            uint32_t b[3][2];
#pragma unroll
            for (int nt = 0; nt < 3; nt++) {
                uint32_t eo = b_eoff + (uint32_t)(ks * 16 * BS_STRIDE + nt * 8) * 2;
                ldsm_x2t(b[nt], BB[s] + eo);
            }
#pragma unroll
            for (int nt = 0; nt < 3; nt++)
                mma_f16(acc[nt], a, b[nt]);
        }

        if (i + 1 < NCHUNK) {
            asm volatile("cp.async.wait_group 0;" ::: "memory");
            __syncthreads();
        }
    }

    // epilogue: silu -> out[:, :128], sigmoid -> g_G
#pragma unroll
    for (int nt = 0; nt < 3; nt++) {
        int r = row0 + wm * 16 + (lane >> 2);
        int c = n0 + wn * 24 + nt * 8 + (lane & 3) * 2;
#pragma unroll
        for (int q = 0; q < 4; q++) {
            int rr = r + (q >> 1) * 8;
            int cc = c + (q & 1);
            float s = acc[nt][q];
            float sg = 1.0f / (1.0f + __expf(-s));
            if (cc < 128) out[(size_t)rr * XDIM + cc] = s * sg;
            else          g_G[rr * 64 + (cc - 128)] = sg;
        }
    }
}

// ---- vectors: M-split (BM=32), grid 256, 512 threads ---------------------------
// v111[b,w,k] = cross_k feats [8192 x 2048] @ WVA[2048 x 64] (3 comps, fp16)
#define V_AS 72
#define V_BS 72
#define VS_XS 0                                   // 32 x 196 f32
#define VS_A  25088                               // 6 bufs: [st][comp], 4608 each
#define VS_B  52736                               // 2 bufs: [st], 9216 each
#define VS_SMEM 71168
#define VA_OFF(st, comp)  (VS_A + (((st) * 3) + (comp)) * 4608)
#define VB_OFF(st)        (VS_B + (st) * 9216)

__global__ void __launch_bounds__(512) vectors_tc(const float* __restrict__ x,
                                                  float* __restrict__ out) {
    extern __shared__ char vsm[];
    float* Xs = (float*)(vsm + VS_XS);
    const int t = threadIdx.x;
    const int lane = t & 31, warp = t >> 5;
    const int wm = warp & 1, wn = warp >> 1;       // 2 x 8
    const int row0 = blockIdx.x * 32;

    uint32_t sb;
    asm("{ .reg .u64 u; cvta.to.shared.u64 u, %1; cvt.u32.u64 %0, u; }"
        : "=r"(sb) : "l"(vsm));

    for (int i = t; i < 32 * 48; i += 512) {
        int r = i / 48, c4 = (i - r * 48) << 2;
        *(float4*)&Xs[r * 196 + c4] =
            *(const float4*)&x[(size_t)(row0 + r) * XDIM + 128 + c4];
    }
    __syncthreads();

    const int kk2 = lane * 2;
    const int mg = warp * 2;

    auto build_A = [&](int c, int st) {
        char* a0p = vsm + VA_OFF(st, 0);
        char* a1p = vsm + VA_OFF(st, 1);
        char* a2p = vsm + VA_OFF(st, 2);
        int kg = c * 64 + kk2;
        uint32_t pk = __ldg((const uint32_t*)&g_pa[kg]);
        int u0 = (pk >> 8) & 255, v0 = pk & 255;
        int u1 = pk >> 24,       v1 = (pk >> 16) & 255;
#pragma unroll
        for (int j = 0; j < 2; j++) {
            int m = mg + j;
            const float* Xr = Xs + m * 196;
            const float* pu = Xr + 3 * u0; const float* pv = Xr + 3 * v0;
            float ax = pu[0], ay = pu[1], az = pu[2];
            float bx = pv[0], by = pv[1], bz = pv[2];
            float c00 = ay * bz - az * by;
            float c01 = az * bx - ax * bz;
            float c02 = ax * by - ay * bx;
            pu = Xr + 3 * u1; pv = Xr + 3 * v1;
            ax = pu[0]; ay = pu[1]; az = pu[2];
            bx = pv[0]; by = pv[1]; bz = pv[2];
            float c10 = ay * bz - az * by;
            float c11 = az * bx - ax * bz;
            float c12 = ax * by - ay * bx;
            int doff = m * (V_AS * 2) + kk2 * 2;
            *(uint32_t*)(a0p + doff) = pack_f16x2(c00, c10);
            *(uint32_t*)(a1p + doff) = pack_f16x2(c01, c11);
            *(uint32_t*)(a2p + doff) = pack_f16x2(c02, c12);
        }
    };
    auto fetch_B = [&](int c, int st) {
        const uint32_t bb = sb + VB_OFF(st);
        int r = t >> 3, cc = (t & 7) * 8;
        uint32_t doff = (uint32_t)(r * (V_BS * 2) + cc * 2);
        cp16(bb + doff, g_WVA + (size_t)(c * 64 + r) * NVD + cc);
        asm volatile("cp.async.commit_group;" ::: "memory");
    };

    float acc[3][4];
#pragma unroll
    for (int cp = 0; cp < 3; cp++)
#pragma unroll
        for (int q = 0; q < 4; q++) acc[cp][q] = 0.0f;

    const uint32_t a_eoff = (uint32_t)((wm * 16 + (lane & 15)) * V_AS +
                                       (lane >> 4) * 8) * 2;
    const uint32_t b_eoff = (uint32_t)((lane & 15) * V_BS + wn * 8) * 2;

    fetch_B(0, 0);
    build_A(0, 0);
    asm volatile("cp.async.wait_group 0;" ::: "memory");
    __syncthreads();

    for (int i = 0; i < NCHV; i++) {
        const int s = i & 1;
        if (i + 1 < NCHV) {
            fetch_B(i + 1, s ^ 1);
            build_A(i + 1, s ^ 1);
        }

#pragma unroll
        for (int ks = 0; ks < 4; ks++) {
            uint32_t b[2];
            uint32_t eo_b = b_eoff + (uint32_t)(ks * 16 * V_BS) * 2;
            ldsm_x2t(b, sb + VB_OFF(s) + eo_b);
#pragma unroll
            for (int cp = 0; cp < 3; cp++) {
                uint32_t a[4];
                uint32_t eo = a_eoff + (uint32_t)(ks * 16) * 2;
                ldsm_x4(a, sb + VA_OFF(s, cp) + eo);
                mma_f16(acc[cp], a, b);
            }
        }

        if (i + 1 < NCHV) {
            asm volatile("cp.async.wait_group 0;" ::: "memory");
            __syncthreads();
        }
    }

    // epilogue: + v011 from transposed fp16 Z, gate, store
#pragma unroll
    for (int qp = 0; qp < 2; qp++) {
        int rloc = wm * 16 + (lane >> 2) + qp * 8;
        int rr = row0 + rloc;
        int cc = wn * 8 + (lane & 3) * 2;
        float v0[3], v1[3];
#pragma unroll
        for (int cp = 0; cp < 3; cp++) {
            v0[cp] = acc[cp][qp * 2];
            v1[cp] = acc[cp][qp * 2 + 1];
        }
        const float* Xr = Xs + rloc * 196;
        const uint4* z0q = (const uint4*)(g_Zh + (size_t)rr * 4096 + cc * 64);
        const uint4* z1q = z0q + 8;
#pragma unroll
        for (int q = 0; q < 8; q++) {
            uint4 za = z0q[q], zb = z1q[q];
            uint32_t wa[4] = {za.x, za.y, za.z, za.w};
            uint32_t wb[4] = {zb.x, zb.y, zb.z, zb.w};
            const float* Xn = Xr + q * 24;
#pragma unroll
            for (int h = 0; h < 4; h++) {
                float2 z0 = h2f(wa[h]);
                float2 z1 = h2f(wb[h]);
                const float* Xp = Xn + h * 6;
                v0[0] += Xp[0] * z0.x + Xp[3] * z0.y;
                v0[1] += Xp[1] * z0.x + Xp[4] * z0.y;
                v0[2] += Xp[2] * z0.x + Xp[5] * z0.y;
                v1[0] += Xp[0] * z1.x + Xp[3] * z1.y;
                v1[1] += Xp[1] * z1.x + Xp[4] * z1.y;
                v1[2] += Xp[2] * z1.x + Xp[5] * z1.y;
            }
        }
        float g0 = g_G[rr * 64 + cc];
        float g1 = g_G[rr * 64 + cc + 1];
        float* orow = out + (size_t)rr * XDIM + 128;
#pragma unroll
        for (int k = 0; k < 3; k++) {
            orow[cc * 3 + k]       = v0[k] * g0;
            orow[(cc + 1) * 3 + k] = v1[k] * g1;
        }
    }
}

// ---------------------------------------------------------------------------
extern "C" void kernel_launch(void* const* d_in, const int* in_sizes, int n_in,
                              void* d_out, int out_size) {
    const float* x = 0;
    const float* w000 = 0;
    const float* w110 = 0;
    const float* w011 = 0;
    const float* w111 = 0;
    for (int i = 0; i < n_in; i++) {
        switch (in_sizes[i]) {
            case BATCH * XDIM:       x    = (const float*)d_in[i]; break;
            case NN0 * NN0 * NSV:    w000 = (const float*)d_in[i]; break;
            case NN1 * NN1 * NSV:    w110 = (const float*)d_in[i]; break;
            case NN0 * NN1 * NVD:    w011 = (const float*)d_in[i]; break;
            case NN1 * NN1 * NVD:    w111 = (const float*)d_in[i]; break;
            default: break;
        }
    }
    if (!x)    x    = (const float*)d_in[0];
    if (!w000) w000 = (const float*)d_in[1];
    if (!w110) w110 = (const float*)d_in[2];
    if (!w011) w011 = (const float*)d_in[3];
    if (!w111) w111 = (const float*)d_in[4];
    float* out = (float*)d_out;

    cudaFuncSetAttribute(scalars_tc14,
                         cudaFuncAttributeMaxDynamicSharedMemorySize, TC_SMEM);
    cudaFuncSetAttribute(g3_tc,
                         cudaFuncAttributeMaxDynamicSharedMemorySize, G3T_SMEM);
    cudaFuncSetAttribute(vectors_tc,
                         cudaFuncAttributeMaxDynamicSharedMemorySize, VS_SMEM);

    build_pairs<<<(KSC_PAD + 255) / 256, 256>>>();
    build_wsc<<<KSC_PAD, NSV>>>(w000, w110);
    build_wva<<<NPA_PAD, NVD>>>(w111);
    build_w3<<<NN0, 1024>>>(w011);
    g3_tc<<<dim3(BATCH / 64, 4096 / 128), 256, G3T_SMEM>>>(x);
    scalars_tc14<<<dim3(BATCH / 64, 2), 512, TC_SMEM>>>(x, out);
    vectors_tc<<<BATCH / 32, 512, VS_SMEM>>>(x, out);
}

// round 16
// speedup vs baseline: 1.1730x; 1.1730x over previous
#include <cuda_runtime.h>
#include <cuda_fp16.h>
#include <math.h>
#include <stdint.h>

// ---------------------------------------------------------------------------
// PE_GatedBlock: B=8192, N0=128, N1=64, NS=128, NV=64
//   scalars = [sym-pair feats x0 | sym-dot feats x1] @ WSC   (mma.sync fp16)
//   Zt = (1/128) x0 @ w011  (TRANSPOSED layout [b][w*64+v], fp16)
//   v111 = cross feats @ WVA                                 (mma.sync fp16)
//   v011 from Zt contraction (fp32 epilogue, contiguous fp16 reads), gating fused.
//   out = [silu(s[:,:128]) | (v111+v011)*sigmoid(s[:,128:])]
// Precision: fp16 operands, fp32 accumulate (measured rel_err 3.28e-4 vs 1e-3).
// R15 lesson: N/M-splitting for occupancy REGRESSES (feature build duplicated,
// warp-tile amortization lost) -> this is the round-14 config + build_w3 fix.
// NOTE: harness ptxas targets sm_103 (no 'a') -> tcgen05 unavailable; mma.sync.
// ---------------------------------------------------------------------------

#define BATCH   8192
#define XDIM    320
#define NN0     128
#define NN1     64
#define NSV     192
#define NVD     64

#define NP0     8256
#define NP1     2080
#define NPA     2016
#define NPA_PAD 2048
#define NCHV    32
#define KSC     (NP0 + NP1)          // 10336
#define KSC_PAD 10368                // 162*64 ; NP0 = 129*64 exactly
#define NCHUNK  162
#define NCH0    129

// ---- static device scratch -------------------------------------------------
__device__ __align__(16) __half g_WSC[KSC_PAD * NSV];    // [k][n]
__device__ __align__(16) __half g_W3[NN0 * NN1 * NVD];   // [u][w*64+v]
__device__ __align__(16) __half g_WVA[NPA_PAD * NVD];    // [p][w]
__device__ __align__(4) unsigned short g_sp[KSC_PAD];
__device__ __align__(4) unsigned short g_pa[NPA_PAD];
__device__ __align__(16) __half g_Zh[(size_t)BATCH * NN1 * NVD];  // [b][w*64+v]
__device__ float g_G[BATCH * NVD];

// ---- triangular index helpers ----------------------------------------------
__device__ __forceinline__ void tri_le(int p, int& u, int& v) {
    int vv = (int)floorf((sqrtf(8.0f * (float)p + 1.0f) - 1.0f) * 0.5f);
    while ((vv + 1) * (vv + 2) / 2 <= p) vv++;
    while (vv * (vv + 1) / 2 > p) vv--;
    v = vv;
    u = p - vv * (vv + 1) / 2;
}
__device__ __forceinline__ void tri_lt(int p, int& u, int& v) {
    int vv = (int)floorf((1.0f + sqrtf(8.0f * (float)p + 1.0f)) * 0.5f);
    while ((vv + 1) * vv / 2 <= p) vv++;
    while (vv * (vv - 1) / 2 > p) vv--;
    v = vv;
    u = p - vv * (vv - 1) / 2;
}

__device__ __forceinline__ uint32_t pack_f16x2(float f0, float f1) {
    __half2 h2 = __floats2half2_rn(f0, f1);
    return *(uint32_t*)&h2;
}
__device__ __forceinline__ float2 h2f(uint32_t u) {
    __half2 h = *(__half2*)&u;
    return __half22float2(h);
}

// ---- pair lists ---------------------------------------------------------------
__global__ void build_pairs() {
    int p = blockIdx.x * blockDim.x + threadIdx.x;
    if (p < KSC_PAD) {
        unsigned short pk = 0;
        if (p < NP0) {
            int u, v; tri_le(p, u, v);
            pk = (unsigned short)((u << 8) | v);
        } else if (p < KSC) {
            int u, v; tri_le(p - NP0, u, v);
            pk = (unsigned short)((u << 8) | v);
        }
        g_sp[p] = pk;
    }
    if (p < NPA_PAD) {
        unsigned short pk = 0;
        if (p < NPA) {
            int u, v; tri_lt(p, u, v);
            pk = (unsigned short)((u << 8) | v);
        }
        g_pa[p] = pk;
    }
}

// ---- weight folding -------------------------------------------------------------
__global__ void build_wsc(const float* __restrict__ w000,
                          const float* __restrict__ w110) {
    int p = blockIdx.x;
    int w = threadIdx.x;
    const float inv_sqrt2 = 0.7071067811865476f;
    float f = 0.0f;
    unsigned int pk = g_sp[p];
    int u = pk >> 8, v = pk & 255;
    if (p < NP0) {
        float val = w000[(u * NN0 + v) * NSV + w];
        if (u != v) val += w000[(v * NN0 + u) * NSV + w];
        f = (inv_sqrt2 / 128.0f) * val;
    } else if (p < KSC) {
        float val = w110[(u * NN1 + v) * NSV + w];
        if (u != v) val += w110[(v * NN1 + u) * NSV + w];
        f = (inv_sqrt2 / (64.0f * 1.7320508075688772f)) * val;
    }
    g_WSC[p * NSV + w] = __float2half_rn(f);
}

__global__ void build_wva(const float* __restrict__ w111) {
    int p = blockIdx.x;
    int w = threadIdx.x;
    float f = 0.0f;
    unsigned int pk = g_pa[p];
    int u = pk >> 8, v = pk & 255;
    if (p < NPA) {
        f = (1.0f / 128.0f) *
            (w111[(u * NN1 + v) * NVD + w] - w111[(v * NN1 + u) * NVD + w]);
    }
    g_WVA[p * NVD + w] = __float2half_rn(f);
}

// w011[u][v][w] -> g_W3[u][w*64+v] via smem transpose, 1024 threads (r15-validated)
__global__ void build_w3(const float* __restrict__ w011) {
    __shared__ float tile[64][65];
    int u = blockIdx.x;
    const float* src = w011 + (size_t)u * 4096;
    for (int i = threadIdx.x; i < 4096; i += 1024) {
        int v = i >> 6, w = i & 63;
        tile[v][w] = src[i];
    }
    __syncthreads();
    __half* dst = g_W3 + (size_t)u * 4096;
    for (int i = threadIdx.x; i < 4096; i += 1024) {
        int w = i >> 6, v = i & 63;
        dst[i] = __float2half_rn(tile[v][w] * (1.0f / 128.0f));
    }
}

// ---- mma.sync helpers --------------------------------------------------------
__device__ __forceinline__ void mma_f16(float* d, const uint32_t* a, const uint32_t* b) {
    asm volatile(
        "mma.sync.aligned.m16n8k16.row.col.f32.f16.f16.f32 "
        "{%0,%1,%2,%3}, {%4,%5,%6,%7}, {%8,%9}, {%0,%1,%2,%3};\n"
        : "+f"(d[0]), "+f"(d[1]), "+f"(d[2]), "+f"(d[3])
        : "r"(a[0]), "r"(a[1]), "r"(a[2]), "r"(a[3]), "r"(b[0]), "r"(b[1]));
}
__device__ __forceinline__ void ldsm_x4(uint32_t* r, uint32_t addr) {
    asm volatile("ldmatrix.sync.aligned.m8n8.x4.shared.b16 {%0,%1,%2,%3}, [%4];"
                 : "=r"(r[0]), "=r"(r[1]), "=r"(r[2]), "=r"(r[3]) : "r"(addr));
}
__device__ __forceinline__ void ldsm_x2t(uint32_t* r, uint32_t addr) {
    asm volatile("ldmatrix.sync.aligned.m8n8.x2.trans.shared.b16 {%0,%1}, [%2];"
                 : "=r"(r[0]), "=r"(r[1]) : "r"(addr));
}
__device__ __forceinline__ void cp16(uint32_t dst, const void* src) {
    asm volatile("cp.async.cg.shared.global [%0], [%1], 16;"
                 :: "r"(dst), "l"(src) : "memory");
}

// ---- g3 on tensor cores: g_Zh = x0[8192x128] @ W3[128x4096] (fp16 out) -------
#define G3_AS  136
#define G3_BS  136
#define G3_A   0
#define G3_B   17408
#define G3T_SMEM 52224

__global__ void __launch_bounds__(256) g3_tc(const float* __restrict__ x) {
    extern __shared__ char g3m[];
    const int t = threadIdx.x;
    const int lane = t & 31, warp = t >> 5;
    const int wm = warp & 1, wn = warp >> 1;
    const int row0 = blockIdx.x * 64;
    const int col0 = blockIdx.y * 128;

    uint32_t sb;
    asm("{ .reg .u64 u; cvta.to.shared.u64 u, %1; cvt.u32.u64 %0, u; }"
        : "=r"(sb) : "l"(g3m));

#pragma unroll
    for (int j = 0; j < 8; j++) {
        int i = t + j * 256;
        int r = i >> 4, cc = (i & 15) * 8;
        uint32_t doff = (uint32_t)(r * (G3_BS * 2) + cc * 2);
        cp16(sb + G3_B + doff, g_W3 + (size_t)r * 4096 + col0 + cc);
    }
    asm volatile("cp.async.commit_group;" ::: "memory");

    for (int i = t; i < 4096; i += 256) {
        int r = i >> 6, c2 = (i & 63) * 2;
        const float* xp = x + (size_t)(row0 + r) * XDIM + c2;
        *(uint32_t*)(g3m + G3_A + r * (G3_AS * 2) + c2 * 2) = pack_f16x2(xp[0], xp[1]);
    }
    asm volatile("cp.async.wait_group 0;" ::: "memory");
    __syncthreads();

    float acc[2][4][4];
#pragma unroll
    for (int mt = 0; mt < 2; mt++)
#pragma unroll
        for (int nt = 0; nt < 4; nt++)
#pragma unroll
            for (int q = 0; q < 4; q++) acc[mt][nt][q] = 0.0f;

    const uint32_t a_eoff = (uint32_t)((wm * 32 + (lane & 15)) * G3_AS +
                                       (lane >> 4) * 8) * 2;
    const uint32_t b_eoff = (uint32_t)((lane & 15) * G3_BS + wn * 32) * 2;

#pragma unroll
    for (int ks = 0; ks < 8; ks++) {
        uint32_t a[2][4];
#pragma unroll
        for (int mt = 0; mt < 2; mt++) {
            uint32_t eo = a_eoff + (uint32_t)(mt * 16 * G3_AS + ks * 16) * 2;
            ldsm_x4(a[mt], sb + G3_A + eo);
        }
        uint32_t b[4][2];
#pragma unroll
        for (int nt = 0; nt < 4; nt++) {
            uint32_t eo = b_eoff + (uint32_t)(ks * 16 * G3_BS + nt * 8) * 2;
            ldsm_x2t(b[nt], sb + G3_B + eo);
        }
#pragma unroll
        for (int mt = 0; mt < 2; mt++)
#pragma unroll
            for (int nt = 0; nt < 4; nt++)
                mma_f16(acc[mt][nt], a[mt], b[nt]);
    }

#pragma unroll
    for (int mt = 0; mt < 2; mt++)
#pragma unroll
        for (int nt = 0; nt < 4; nt++) {
            int r = row0 + wm * 32 + mt * 16 + (lane >> 2);
            int c = col0 + wn * 32 + nt * 8 + (lane & 3) * 2;
            *(uint32_t*)&g_Zh[(size_t)r * 4096 + c] =
                pack_f16x2(acc[mt][nt][0], acc[mt][nt][1]);
            *(uint32_t*)&g_Zh[(size_t)(r + 8) * 4096 + c] =
                pack_f16x2(acc[mt][nt][2], acc[mt][nt][3]);
        }
}

// ---- scalars: pipelined mma.sync GEMM, 512 threads ----------------------------
#define AS_STRIDE 72      // fp16; 144B rows -> ldmatrix conflict-free
#define BS_STRIDE 216     // fp16; 432B rows -> ldmatrix conflict-free

#define SM_XS   0                           // p1: 64x132 f32; p2: 64x196 f32
#define SM_A0   50176
#define SM_A1   59392
#define SM_B0   68608
#define SM_B1   96256
#define TC_SMEM 123904

__global__ void __launch_bounds__(512) scalars_tc12(const float* __restrict__ x,
                                                    float* __restrict__ out) {
    extern __shared__ char tcsm[];
    float* Xs = (float*)(tcsm + SM_XS);
    const int t = threadIdx.x;
    const int lane = t & 31, warp = t >> 5;
    const int wm = warp & 1, wn = warp >> 1;       // 2 x 8
    const int row0 = blockIdx.x * 64;

    uint32_t sb;
    asm("{ .reg .u64 u; cvta.to.shared.u64 u, %1; cvt.u32.u64 %0, u; }"
        : "=r"(sb) : "l"(tcsm));

    const uint32_t AA[2] = {sb + SM_A0, sb + SM_A1};
    const uint32_t BB[2] = {sb + SM_B0, sb + SM_B1};

    for (int i = t; i < 64 * 32; i += 512) {
        int r = i >> 5, c4 = (i & 31) << 2;
        *(float4*)&Xs[r * 132 + c4] =
            *(const float4*)&x[(size_t)(row0 + r) * XDIM + c4];
    }
    __syncthreads();

    const int kk2 = lane * 2;
    const int mg = warp * 4;

    auto build_A = [&](int c, int st) {
        char* aa = tcsm + (st ? SM_A1 : SM_A0);
        int kg = c * 64 + kk2;
        uint32_t pk = __ldg((const uint32_t*)&g_sp[kg]);
        int u0 = (pk >> 8) & 255, v0 = pk & 255;
        int u1 = pk >> 24,       v1 = (pk >> 16) & 255;
        if (c < NCH0) {
#pragma unroll
            for (int j = 0; j < 4; j++) {
                int m = mg + j;
                const float* Xr = Xs + m * 132;
                *(uint32_t*)(aa + m * (AS_STRIDE * 2) + kk2 * 2) =
                    pack_f16x2(Xr[u0] * Xr[v0], Xr[u1] * Xr[v1]);
            }
        } else {
#pragma unroll
            for (int j = 0; j < 4; j++) {
                int m = mg + j;
                const float* Xr = Xs + m * 196;
                const float* a0 = Xr + 3 * u0; const float* b0 = Xr + 3 * v0;
                const float* a1 = Xr + 3 * u1; const float* b1 = Xr + 3 * v1;
                float f0 = a0[0] * b0[0] + a0[1] * b0[1] + a0[2] * b0[2];
                float f1 = a1[0] * b1[0] + a1[1] * b1[1] + a1[2] * b1[2];
                *(uint32_t*)(aa + m * (AS_STRIDE * 2) + kk2 * 2) = pack_f16x2(f0, f1);
            }
        }
    };
    // B tile: 64 rows x 192 fp16 = 1536 16B-chunks
    auto fetch_B = [&](int c, int st) {
        const uint32_t bb = BB[st];
        const int k0 = c * 64;
#pragma unroll
        for (int j = 0; j < 3; j++) {
            int i = t + j * 512;
            int r = i / 24, cc = (i - r * 24) * 8;
            uint32_t doff = (uint32_t)(r * (BS_STRIDE * 2) + cc * 2);
            cp16(bb + doff, g_WSC + (size_t)(k0 + r) * NSV + cc);
        }
        asm volatile("cp.async.commit_group;" ::: "memory");
    };

    float acc[2][3][4];
#pragma unroll
    for (int mt = 0; mt < 2; mt++)
#pragma unroll
        for (int nt = 0; nt < 3; nt++)
#pragma unroll
            for (int q = 0; q < 4; q++) acc[mt][nt][q] = 0.0f;

    const uint32_t a_eoff = (uint32_t)((wm * 32 + (lane & 15)) * AS_STRIDE +
                                       (lane >> 4) * 8) * 2;
    const uint32_t b_eoff = (uint32_t)((lane & 15) * BS_STRIDE + wn * 24) * 2;

    fetch_B(0, 0);
    build_A(0, 0);
    asm volatile("cp.async.wait_group 0;" ::: "memory");
    __syncthreads();

    for (int i = 0; i < NCHUNK; i++) {
        const int s = i & 1;
        if (i + 1 < NCHUNK) {
            if (i + 1 == NCH0) {
                for (int j = t; j < 64 * 48; j += 512) {
                    int r = j / 48, c4 = (j - r * 48) << 2;
                    *(float4*)&Xs[r * 196 + c4] =
                        *(const float4*)&x[(size_t)(row0 + r) * XDIM + 128 + c4];
                }
                __syncthreads();
            }
            fetch_B(i + 1, s ^ 1);
            build_A(i + 1, s ^ 1);
        }

#pragma unroll
        for (int ks = 0; ks < 4; ks++) {
            uint32_t a[2][4];
#pragma unroll
            for (int mt = 0; mt < 2; mt++) {
                uint32_t eo = a_eoff + (uint32_t)(mt * 16 * AS_STRIDE + ks * 16) * 2;
                ldsm_x4(a[mt], AA[s] + eo);
            }
            uint32_t b[3][2];
#pragma unroll
            for (int nt = 0; nt < 3; nt++) {
                uint32_t eo = b_eoff + (uint32_t)(ks * 16 * BS_STRIDE + nt * 8) * 2;
                ldsm_x2t(b[nt], BB[s] + eo);
            }
#pragma unroll
            for (int mt = 0; mt < 2; mt++)
#pragma unroll
                for (int nt = 0; nt < 3; nt++)
                    mma_f16(acc[mt][nt], a[mt], b[nt]);
        }

        if (i + 1 < NCHUNK) {
            asm volatile("cp.async.wait_group 0;" ::: "memory");
            __syncthreads();
        }
    }

    // epilogue: silu -> out[:, :128], sigmoid -> g_G
#pragma unroll
    for (int mt = 0; mt < 2; mt++) {
#pragma unroll
        for (int nt = 0; nt < 3; nt++) {
            int r = row0 + wm * 32 + mt * 16 + (lane >> 2);
            int c = wn * 24 + nt * 8 + (lane & 3) * 2;
#pragma unroll
            for (int q = 0; q < 4; q++) {
                int rr = r + (q >> 1) * 8;
                int cc = c + (q & 1);
                float s = acc[mt][nt][q];
                float sg = 1.0f / (1.0f + __expf(-s));
                if (cc < 128) out[(size_t)rr * XDIM + cc] = s * sg;
                else          g_G[rr * 64 + (cc - 128)] = sg;
            }
        }
    }
}

// ---- vectors on tensor cores ---------------------------------------------------
// v111[b,w,k] = cross_k feats [8192 x 2048] @ WVA[2048 x 64]  (3 comps, fp16)
#define V_AS 72
#define V_BS 72
#define VS_XS 0                                   // 64 x 196 f32 (x1 rows)
#define VS_A  50176                               // 6 bufs: [st][comp]
#define VS_B  105472                              // 2 bufs: [st]
#define VS_SMEM 123904
#define VA_OFF(st, comp)  (VS_A + (((st) * 3) + (comp)) * 9216)
#define VB_OFF(st)        (VS_B + (st) * 9216)

__global__ void __launch_bounds__(512) vectors_tc(const float* __restrict__ x,
                                                  float* __restrict__ out) {
    extern __shared__ char vsm[];
    float* Xs = (float*)(vsm + VS_XS);
    const int t = threadIdx.x;
    const int lane = t & 31, warp = t >> 5;
    const int wm = warp & 1, wn = warp >> 1;       // 2 x 8
    const int row0 = blockIdx.x * 64;

    uint32_t sb;
    asm("{ .reg .u64 u; cvta.to.shared.u64 u, %1; cvt.u32.u64 %0, u; }"
        : "=r"(sb) : "l"(vsm));

    for (int i = t; i < 64 * 48; i += 512) {
        int r = i / 48, c4 = (i - r * 48) << 2;
        *(float4*)&Xs[r * 196 + c4] =
            *(const float4*)&x[(size_t)(row0 + r) * XDIM + 128 + c4];
    }
    __syncthreads();

    const int kk2 = lane * 2;
    const int mg = warp * 4;

    auto build_A = [&](int c, int st) {
        char* a0p = vsm + VA_OFF(st, 0);
        char* a1p = vsm + VA_OFF(st, 1);
        char* a2p = vsm + VA_OFF(st, 2);
        int kg = c * 64 + kk2;
        uint32_t pk = __ldg((const uint32_t*)&g_pa[kg]);
        int u0 = (pk >> 8) & 255, v0 = pk & 255;
        int u1 = pk >> 24,       v1 = (pk >> 16) & 255;
#pragma unroll
        for (int j = 0; j < 4; j++) {
            int m = mg + j;
            const float* Xr = Xs + m * 196;
            const float* pu = Xr + 3 * u0; const float* pv = Xr + 3 * v0;
            float ax = pu[0], ay = pu[1], az = pu[2];
            float bx = pv[0], by = pv[1], bz = pv[2];
            float c00 = ay * bz - az * by;
            float c01 = az * bx - ax * bz;
            float c02 = ax * by - ay * bx;
            pu = Xr + 3 * u1; pv = Xr + 3 * v1;
            ax = pu[0]; ay = pu[1]; az = pu[2];
            bx = pv[0]; by = pv[1]; bz = pv[2];
            float c10 = ay * bz - az * by;
            float c11 = az * bx - ax * bz;
            float c12 = ax * by - ay * bx;
            int doff = m * (V_AS * 2) + kk2 * 2;
            *(uint32_t*)(a0p + doff) = pack_f16x2(c00, c10);
            *(uint32_t*)(a1p + doff) = pack_f16x2(c01, c11);
            *(uint32_t*)(a2p + doff) = pack_f16x2(c02, c12);
        }
    };
    auto fetch_B = [&](int c, int st) {
        const uint32_t bb = sb + VB_OFF(st);
        int r = t >> 3, cc = (t & 7) * 8;
        uint32_t doff = (uint32_t)(r * (V_BS * 2) + cc * 2);
        cp16(bb + doff, g_WVA + (size_t)(c * 64 + r) * NVD + cc);
        asm volatile("cp.async.commit_group;" ::: "memory");
    };

    float acc[2][3][4];
#pragma unroll
    for (int mt = 0; mt < 2; mt++)
#pragma unroll
        for (int cp = 0; cp < 3; cp++)
#pragma unroll
            for (int q = 0; q < 4; q++) acc[mt][cp][q] = 0.0f;

    const uint32_t a_eoff = (uint32_t)((wm * 32 + (lane & 15)) * V_AS +
                                       (lane >> 4) * 8) * 2;
    const uint32_t b_eoff = (uint32_t)((lane & 15) * V_BS + wn * 8) * 2;

    fetch_B(0, 0);
    build_A(0, 0);
    asm volatile("cp.async.wait_group 0;" ::: "memory");
    __syncthreads();

    for (int i = 0; i < NCHV; i++) {
        const int s = i & 1;
        if (i + 1 < NCHV) {
            fetch_B(i + 1, s ^ 1);
            build_A(i + 1, s ^ 1);
        }

#pragma unroll
        for (int ks = 0; ks < 4; ks++) {
            uint32_t b[2];
            uint32_t eo_b = b_eoff + (uint32_t)(ks * 16 * V_BS) * 2;
            ldsm_x2t(b, sb + VB_OFF(s) + eo_b);
#pragma unroll
            for (int cp = 0; cp < 3; cp++) {
#pragma unroll
                for (int mt = 0; mt < 2; mt++) {
                    uint32_t a[4];
                    uint32_t eo = a_eoff + (uint32_t)(mt * 16 * V_AS + ks * 16) * 2;
                    ldsm_x4(a, sb + VA_OFF(s, cp) + eo);
                    mma_f16(acc[mt][cp], a, b);
                }
            }
        }

        if (i + 1 < NCHV) {
            asm volatile("cp.async.wait_group 0;" ::: "memory");
            __syncthreads();
        }
    }

    // epilogue: + v011 from transposed fp16 Z (contiguous reads), gate, store
#pragma unroll
    for (int mt = 0; mt < 2; mt++) {
#pragma unroll
        for (int qp = 0; qp < 2; qp++) {
            int rloc = wm * 32 + mt * 16 + (lane >> 2) + qp * 8;
            int rr = row0 + rloc;
            int cc = wn * 8 + (lane & 3) * 2;
            float v0[3], v1[3];
#pragma unroll
            for (int cp = 0; cp < 3; cp++) {
                v0[cp] = acc[mt][cp][qp * 2];
                v1[cp] = acc[mt][cp][qp * 2 + 1];
            }
            const float* Xr = Xs + rloc * 196;
            const uint4* z0q = (const uint4*)(g_Zh + (size_t)rr * 4096 + cc * 64);
            const uint4* z1q = z0q + 8;
#pragma unroll
            for (int q = 0; q < 8; q++) {
                uint4 za = z0q[q], zb = z1q[q];
                uint32_t wa[4] = {za.x, za.y, za.z, za.w};
                uint32_t wb[4] = {zb.x, zb.y, zb.z, zb.w};
                const float* Xn = Xr + q * 24;
#pragma unroll
                for (int h = 0; h < 4; h++) {
                    float2 z0 = h2f(wa[h]);
                    float2 z1 = h2f(wb[h]);
                    const float* Xp = Xn + h * 6;
                    v0[0] += Xp[0] * z0.x + Xp[3] * z0.y;
                    v0[1] += Xp[1] * z0.x + Xp[4] * z0.y;
                    v0[2] += Xp[2] * z0.x + Xp[5] * z0.y;
                    v1[0] += Xp[0] * z1.x + Xp[3] * z1.y;
                    v1[1] += Xp[1] * z1.x + Xp[4] * z1.y;
                    v1[2] += Xp[2] * z1.x + Xp[5] * z1.y;
                }
            }
            float g0 = g_G[rr * 64 + cc];
            float g1 = g_G[rr * 64 + cc + 1];
            float* orow = out + (size_t)rr * XDIM + 128;
#pragma unroll
            for (int k = 0; k < 3; k++) {
                orow[cc * 3 + k]       = v0[k] * g0;
                orow[(cc + 1) * 3 + k] = v1[k] * g1;
            }
        }
    }
}

// ---------------------------------------------------------------------------
extern "C" void kernel_launch(void* const* d_in, const int* in_sizes, int n_in,
                              void* d_out, int out_size) {
    const float* x = 0;
    const float* w000 = 0;
    const float* w110 = 0;
    const float* w011 = 0;
    const float* w111 = 0;
    for (int i = 0; i < n_in; i++) {
        switch (in_sizes[i]) {
            case BATCH * XDIM:       x    = (const float*)d_in[i]; break;
            case NN0 * NN0 * NSV:    w000 = (const float*)d_in[i]; break;
            case NN1 * NN1 * NSV:    w110 = (const float*)d_in[i]; break;
            case NN0 * NN1 * NVD:    w011 = (const float*)d_in[i]; break;
            case NN1 * NN1 * NVD:    w111 = (const float*)d_in[i]; break;
            default: break;
        }
    }
    if (!x)    x    = (const float*)d_in[0];
    if (!w000) w000 = (const float*)d_in[1];
    if (!w110) w110 = (const float*)d_in[2];
    if (!w011) w011 = (const float*)d_in[3];
    if (!w111) w111 = (const float*)d_in[4];
    float* out = (float*)d_out;

    cudaFuncSetAttribute(scalars_tc12,
                         cudaFuncAttributeMaxDynamicSharedMemorySize, TC_SMEM);
    cudaFuncSetAttribute(g3_tc,
                         cudaFuncAttributeMaxDynamicSharedMemorySize, G3T_SMEM);
    cudaFuncSetAttribute(vectors_tc,
                         cudaFuncAttributeMaxDynamicSharedMemorySize, VS_SMEM);

    build_pairs<<<(KSC_PAD + 255) / 256, 256>>>();
    build_wsc<<<KSC_PAD, NSV>>>(w000, w110);
    build_wva<<<NPA_PAD, NVD>>>(w111);
    build_w3<<<NN0, 1024>>>(w011);
    g3_tc<<<dim3(BATCH / 64, 4096 / 128), 256, G3T_SMEM>>>(x);
    scalars_tc12<<<BATCH / 64, 512, TC_SMEM>>>(x, out);
    vectors_tc<<<BATCH / 64, 512, VS_SMEM>>>(x, out);
}

// round 17
// speedup vs baseline: 1.1985x; 1.0217x over previous
#include <cuda_runtime.h>
#include <cuda_fp16.h>
#include <math.h>
#include <stdint.h>

// ---------------------------------------------------------------------------
// PE_GatedBlock: B=8192, N0=128, N1=64, NS=128, NV=64
//   scalars = [sym-pair feats x0 | sym-dot feats x1] @ WSC   (mma.sync fp16)
//   Zt = (1/128) x0 @ w011  (transposed [b][w*64+v], fp16)
//   v111 = cross feats @ WVA (mma.sync fp16)
//   v011 from Zt contraction (fp32 epilogue), gating fused.
//   out = [silu(s[:,:128]) | (v111+v011)*sigmoid(s[:,128:])]
// R16: BK=128 chunks (half the barriers, 2x MMA run length), both x tiles
// resident (no phase switch; mixed chunk 64 splits cleanly at 64-subchunk).
// Precision: fp16 operands, fp32 accumulate (measured rel_err 3.28e-4).
// NOTE: harness ptxas targets sm_103 (no 'a') -> tcgen05 unavailable; mma.sync.
// ---------------------------------------------------------------------------

#define BATCH   8192
#define XDIM    320
#define NN0     128
#define NN1     64
#define NSV     192
#define NVD     64

#define NP0     8256
#define NP1     2080
#define NPA     2016
#define NPA_PAD 2048
#define NCHV    16                   // 2048 / 128
#define KSC     (NP0 + NP1)          // 10336
#define KSC_PAD 10368                // 81*128 exactly
#define NCHUNK  81

// ---- static device scratch -------------------------------------------------
__device__ __align__(16) __half g_WSC[KSC_PAD * NSV];    // [k][n]
__device__ __align__(16) __half g_W3[NN0 * NN1 * NVD];   // [u][w*64+v]
__device__ __align__(16) __half g_WVA[NPA_PAD * NVD];    // [p][w]
__device__ __align__(4) unsigned short g_sp[KSC_PAD];
__device__ __align__(4) unsigned short g_pa[NPA_PAD];
__device__ __align__(16) __half g_Zh[(size_t)BATCH * NN1 * NVD];  // [b][w*64+v]
__device__ float g_G[BATCH * NVD];

// ---- triangular index helpers ----------------------------------------------
__device__ __forceinline__ void tri_le(int p, int& u, int& v) {
    int vv = (int)floorf((sqrtf(8.0f * (float)p + 1.0f) - 1.0f) * 0.5f);
    while ((vv + 1) * (vv + 2) / 2 <= p) vv++;
    while (vv * (vv + 1) / 2 > p) vv--;
    v = vv;
    u = p - vv * (vv + 1) / 2;
}
__device__ __forceinline__ void tri_lt(int p, int& u, int& v) {
    int vv = (int)floorf((1.0f + sqrtf(8.0f * (float)p + 1.0f)) * 0.5f);
    while ((vv + 1) * vv / 2 <= p) vv++;
    while (vv * (vv - 1) / 2 > p) vv--;
    v = vv;
    u = p - vv * (vv - 1) / 2;
}

__device__ __forceinline__ uint32_t pack_f16x2(float f0, float f1) {
    __half2 h2 = __floats2half2_rn(f0, f1);
    return *(uint32_t*)&h2;
}
__device__ __forceinline__ float2 h2f(uint32_t u) {
    __half2 h = *(__half2*)&u;
    return __half22float2(h);
}

// ---- pair lists ---------------------------------------------------------------
__global__ void build_pairs() {
    int p = blockIdx.x * blockDim.x + threadIdx.x;
    if (p < KSC_PAD) {
        unsigned short pk = 0;
        if (p < NP0) {
            int u, v; tri_le(p, u, v);
            pk = (unsigned short)((u << 8) | v);
        } else if (p < KSC) {
            int u, v; tri_le(p - NP0, u, v);
            pk = (unsigned short)((u << 8) | v);
        }
        g_sp[p] = pk;
    }
    if (p < NPA_PAD) {
        unsigned short pk = 0;
        if (p < NPA) {
            int u, v; tri_lt(p, u, v);
            pk = (unsigned short)((u << 8) | v);
        }
        g_pa[p] = pk;
    }
}

// ---- weight folding -------------------------------------------------------------
__global__ void build_wsc(const float* __restrict__ w000,
                          const float* __restrict__ w110) {
    int p = blockIdx.x;
    int w = threadIdx.x;
    const float inv_sqrt2 = 0.7071067811865476f;
    float f = 0.0f;
    unsigned int pk = g_sp[p];
    int u = pk >> 8, v = pk & 255;
    if (p < NP0) {
        float val = w000[(u * NN0 + v) * NSV + w];
        if (u != v) val += w000[(v * NN0 + u) * NSV + w];
        f = (inv_sqrt2 / 128.0f) * val;
    } else if (p < KSC) {
        float val = w110[(u * NN1 + v) * NSV + w];
        if (u != v) val += w110[(v * NN1 + u) * NSV + w];
        f = (inv_sqrt2 / (64.0f * 1.7320508075688772f)) * val;
    }
    g_WSC[p * NSV + w] = __float2half_rn(f);
}

__global__ void build_wva(const float* __restrict__ w111) {
    int p = blockIdx.x;
    int w = threadIdx.x;
    float f = 0.0f;
    unsigned int pk = g_pa[p];
    int u = pk >> 8, v = pk & 255;
    if (p < NPA) {
        f = (1.0f / 128.0f) *
            (w111[(u * NN1 + v) * NVD + w] - w111[(v * NN1 + u) * NVD + w]);
    }
    g_WVA[p * NVD + w] = __float2half_rn(f);
}

// w011[u][v][w] -> g_W3[u][w*64+v] via smem transpose, 1024 threads
__global__ void build_w3(const float* __restrict__ w011) {
    __shared__ float tile[64][65];
    int u = blockIdx.x;
    const float* src = w011 + (size_t)u * 4096;
    for (int i = threadIdx.x; i < 4096; i += 1024) {
        int v = i >> 6, w = i & 63;
        tile[v][w] = src[i];
    }
    __syncthreads();
    __half* dst = g_W3 + (size_t)u * 4096;
    for (int i = threadIdx.x; i < 4096; i += 1024) {
        int w = i >> 6, v = i & 63;
        dst[i] = __float2half_rn(tile[v][w] * (1.0f / 128.0f));
    }
}

// ---- mma.sync helpers --------------------------------------------------------
__device__ __forceinline__ void mma_f16(float* d, const uint32_t* a, const uint32_t* b) {
    asm volatile(
        "mma.sync.aligned.m16n8k16.row.col.f32.f16.f16.f32 "
        "{%0,%1,%2,%3}, {%4,%5,%6,%7}, {%8,%9}, {%0,%1,%2,%3};\n"
        : "+f"(d[0]), "+f"(d[1]), "+f"(d[2]), "+f"(d[3])
        : "r"(a[0]), "r"(a[1]), "r"(a[2]), "r"(a[3]), "r"(b[0]), "r"(b[1]));
}
__device__ __forceinline__ void ldsm_x4(uint32_t* r, uint32_t addr) {
    asm volatile("ldmatrix.sync.aligned.m8n8.x4.shared.b16 {%0,%1,%2,%3}, [%4];"
                 : "=r"(r[0]), "=r"(r[1]), "=r"(r[2]), "=r"(r[3]) : "r"(addr));
}
__device__ __forceinline__ void ldsm_x2t(uint32_t* r, uint32_t addr) {
    asm volatile("ldmatrix.sync.aligned.m8n8.x2.trans.shared.b16 {%0,%1}, [%2];"
                 : "=r"(r[0]), "=r"(r[1]) : "r"(addr));
}
__device__ __forceinline__ void cp16(uint32_t dst, const void* src) {
    asm volatile("cp.async.cg.shared.global [%0], [%1], 16;"
                 :: "r"(dst), "l"(src) : "memory");
}

// ---- g3 on tensor cores: g_Zh = x0[8192x128] @ W3[128x4096] (fp16 out) -------
#define G3_AS  136
#define G3_BS  136
#define G3_A   0
#define G3_B   17408
#define G3T_SMEM 52224

__global__ void __launch_bounds__(256) g3_tc(const float* __restrict__ x) {
    extern __shared__ char g3m[];
    const int t = threadIdx.x;
    const int lane = t & 31, warp = t >> 5;
    const int wm = warp & 1, wn = warp >> 1;
    const int row0 = blockIdx.x * 64;
    const int col0 = blockIdx.y * 128;

    uint32_t sb;
    asm("{ .reg .u64 u; cvta.to.shared.u64 u, %1; cvt.u32.u64 %0, u; }"
        : "=r"(sb) : "l"(g3m));

#pragma unroll
    for (int j = 0; j < 8; j++) {
        int i = t + j * 256;
        int r = i >> 4, cc = (i & 15) * 8;
        uint32_t doff = (uint32_t)(r * (G3_BS * 2) + cc * 2);
        cp16(sb + G3_B + doff, g_W3 + (size_t)r * 4096 + col0 + cc);
    }
    asm volatile("cp.async.commit_group;" ::: "memory");

    for (int i = t; i < 4096; i += 256) {
        int r = i >> 6, c2 = (i & 63) * 2;
        const float* xp = x + (size_t)(row0 + r) * XDIM + c2;
        *(uint32_t*)(g3m + G3_A + r * (G3_AS * 2) + c2 * 2) = pack_f16x2(xp[0], xp[1]);
    }
    asm volatile("cp.async.wait_group 0;" ::: "memory");
    __syncthreads();

    float acc[2][4][4];
#pragma unroll
    for (int mt = 0; mt < 2; mt++)
#pragma unroll
        for (int nt = 0; nt < 4; nt++)
#pragma unroll
            for (int q = 0; q < 4; q++) acc[mt][nt][q] = 0.0f;

    const uint32_t a_eoff = (uint32_t)((wm * 32 + (lane & 15)) * G3_AS +
                                       (lane >> 4) * 8) * 2;
    const uint32_t b_eoff = (uint32_t)((lane & 15) * G3_BS + wn * 32) * 2;

#pragma unroll
    for (int ks = 0; ks < 8; ks++) {
        uint32_t a[2][4];
#pragma unroll
        for (int mt = 0; mt < 2; mt++) {
            uint32_t eo = a_eoff + (uint32_t)(mt * 16 * G3_AS + ks * 16) * 2;
            ldsm_x4(a[mt], sb + G3_A + eo);
        }
        uint32_t b[4][2];
#pragma unroll
        for (int nt = 0; nt < 4; nt++) {
            uint32_t eo = b_eoff + (uint32_t)(ks * 16 * G3_BS + nt * 8) * 2;
            ldsm_x2t(b[nt], sb + G3_B + eo);
        }
#pragma unroll
        for (int mt = 0; mt < 2; mt++)
#pragma unroll
            for (int nt = 0; nt < 4; nt++)
                mma_f16(acc[mt][nt], a[mt], b[nt]);
    }

#pragma unroll
    for (int mt = 0; mt < 2; mt++)
#pragma unroll
        for (int nt = 0; nt < 4; nt++) {
            int r = row0 + wm * 32 + mt * 16 + (lane >> 2);
            int c = col0 + wn * 32 + nt * 8 + (lane & 3) * 2;
            *(uint32_t*)&g_Zh[(size_t)r * 4096 + c] =
                pack_f16x2(acc[mt][nt][0], acc[mt][nt][1]);
            *(uint32_t*)&g_Zh[(size_t)(r + 8) * 4096 + c] =
                pack_f16x2(acc[mt][nt][2], acc[mt][nt][3]);
        }
}

// ---- scalars: BK=128 pipelined mma.sync, 512 threads ----------------------------
#define AS_STRIDE 136     // fp16; 272B rows (16 mod 128) -> ldmatrix conflict-free
#define BS_STRIDE 200     // fp16; 400B rows (16 mod 128) -> ldmatrix conflict-free

#define SM_X0   0                            // 64 x 132 f32 = 33792
#define SM_X1   33792                        // 64 x 196 f32 = 50176
#define SM_A0   83968                        // 64 x 136 fp16 = 17408
#define SM_A1   101376
#define SM_B0   118784                       // 128 x 200 fp16 = 51200
#define SM_B1   169984
#define TC_SMEM 221184

__global__ void __launch_bounds__(512) scalars_tc16(const float* __restrict__ x,
                                                    float* __restrict__ out) {
    extern __shared__ char tcsm[];
    float* Xs0 = (float*)(tcsm + SM_X0);
    float* Xs1 = (float*)(tcsm + SM_X1);
    const int t = threadIdx.x;
    const int lane = t & 31, warp = t >> 5;
    const int wm = warp & 1, wn = warp >> 1;       // 2 x 8
    const int row0 = blockIdx.x * 64;

    uint32_t sb;
    asm("{ .reg .u64 u; cvta.to.shared.u64 u, %1; cvt.u32.u64 %0, u; }"
        : "=r"(sb) : "l"(tcsm));

    const uint32_t AA[2] = {sb + SM_A0, sb + SM_A1};
    const uint32_t BB[2] = {sb + SM_B0, sb + SM_B1};

    // load both x tiles
    for (int i = t; i < 64 * 32; i += 512) {
        int r = i >> 5, c4 = (i & 31) << 2;
        *(float4*)&Xs0[r * 132 + c4] =
            *(const float4*)&x[(size_t)(row0 + r) * XDIM + c4];
    }
    for (int i = t; i < 64 * 48; i += 512) {
        int r = i / 48, c4 = (i - r * 48) << 2;
        *(float4*)&Xs1[r * 196 + c4] =
            *(const float4*)&x[(size_t)(row0 + r) * XDIM + 128 + c4];
    }
    __syncthreads();

    const int kk2 = lane * 2;     // k-pair within 64-subchunk
    const int mg = warp * 4;      // 4 m rows per warp

    // feature tile: [64 m][128 k]; each thread: 4 rows x 2 k-groups
    auto build_A = [&](int c, int st) {
        char* aa = tcsm + (st ? SM_A1 : SM_A0);
        const int k0g = c * 128;
#pragma unroll
        for (int g = 0; g < 2; g++) {
            int kk = g * 64 + kk2;
            int kg = k0g + kk;
            uint32_t pk = __ldg((const uint32_t*)&g_sp[kg]);
            int u0 = (pk >> 8) & 255, v0 = pk & 255;
            int u1 = pk >> 24,       v1 = (pk >> 16) & 255;
            if (kg < NP0) {
#pragma unroll
                for (int j = 0; j < 4; j++) {
                    int m = mg + j;
                    const float* Xr = Xs0 + m * 132;
                    *(uint32_t*)(aa + m * (AS_STRIDE * 2) + kk * 2) =
                        pack_f16x2(Xr[u0] * Xr[v0], Xr[u1] * Xr[v1]);
                }
            } else {
#pragma unroll
                for (int j = 0; j < 4; j++) {
                    int m = mg + j;
                    const float* Xr = Xs1 + m * 196;
                    const float* a0 = Xr + 3 * u0; const float* b0 = Xr + 3 * v0;
                    const float* a1 = Xr + 3 * u1; const float* b1 = Xr + 3 * v1;
                    float f0 = a0[0] * b0[0] + a0[1] * b0[1] + a0[2] * b0[2];
                    float f1 = a1[0] * b1[0] + a1[1] * b1[1] + a1[2] * b1[2];
                    *(uint32_t*)(aa + m * (AS_STRIDE * 2) + kk * 2) =
                        pack_f16x2(f0, f1);
                }
            }
        }
    };
    // B tile: 128 rows x 192 fp16 = 3072 16B-chunks
    auto fetch_B = [&](int c, int st) {
        const uint32_t bb = BB[st];
        const int k0 = c * 128;
#pragma unroll
        for (int j = 0; j < 6; j++) {
            int i = t + j * 512;
            int r = i / 24, cc = (i - r * 24) * 8;
            uint32_t doff = (uint32_t)(r * (BS_STRIDE * 2) + cc * 2);
            cp16(bb + doff, g_WSC + (size_t)(k0 + r) * NSV + cc);
        }
        asm volatile("cp.async.commit_group;" ::: "memory");
    };

    float acc[2][3][4];
#pragma unroll
    for (int mt = 0; mt < 2; mt++)
#pragma unroll
        for (int nt = 0; nt < 3; nt++)
#pragma unroll
            for (int q = 0; q < 4; q++) acc[mt][nt][q] = 0.0f;

    const uint32_t a_eoff = (uint32_t)((wm * 32 + (lane & 15)) * AS_STRIDE +
                                       (lane >> 4) * 8) * 2;
    const uint32_t b_eoff = (uint32_t)((lane & 15) * BS_STRIDE + wn * 24) * 2;

    fetch_B(0, 0);
    build_A(0, 0);
    asm volatile("cp.async.wait_group 0;" ::: "memory");
    __syncthreads();

    for (int i = 0; i < NCHUNK; i++) {
        const int s = i & 1;
        if (i + 1 < NCHUNK) {
            fetch_B(i + 1, s ^ 1);
            build_A(i + 1, s ^ 1);
        }

#pragma unroll
        for (int ks = 0; ks < 8; ks++) {
            uint32_t a[2][4];
#pragma unroll
            for (int mt = 0; mt < 2; mt++) {
                uint32_t eo = a_eoff + (uint32_t)(mt * 16 * AS_STRIDE + ks * 16) * 2;
                ldsm_x4(a[mt], AA[s] + eo);
            }
            uint32_t b[3][2];
#pragma unroll
            for (int nt = 0; nt < 3; nt++) {
                uint32_t eo = b_eoff + (uint32_t)(ks * 16 * BS_STRIDE + nt * 8) * 2;
                ldsm_x2t(b[nt], BB[s] + eo);
            }
#pragma unroll
            for (int mt = 0; mt < 2; mt++)
#pragma unroll
                for (int nt = 0; nt < 3; nt++)
                    mma_f16(acc[mt][nt], a[mt], b[nt]);
        }

        if (i + 1 < NCHUNK) {
            asm volatile("cp.async.wait_group 0;" ::: "memory");
            __syncthreads();
        }
    }

    // epilogue: silu -> out[:, :128], sigmoid -> g_G
#pragma unroll
    for (int mt = 0; mt < 2; mt++) {
#pragma unroll
        for (int nt = 0; nt < 3; nt++) {
            int r = row0 + wm * 32 + mt * 16 + (lane >> 2);
            int c = wn * 24 + nt * 8 + (lane & 3) * 2;
#pragma unroll
            for (int q = 0; q < 4; q++) {
                int rr = r + (q >> 1) * 8;
                int cc = c + (q & 1);
                float s = acc[mt][nt][q];
                float sg = 1.0f / (1.0f + __expf(-s));
                if (cc < 128) out[(size_t)rr * XDIM + cc] = s * sg;
                else          g_G[rr * 64 + (cc - 128)] = sg;
            }
        }
    }
}

// ---- vectors: BK=128, 512 threads -----------------------------------------------
// v111[b,w,k] = cross_k feats [8192 x 2048] @ WVA[2048 x 64] (3 comps, fp16)
#define V_AS 136
#define V_BS 72
#define VS_XS 0                                   // 64 x 196 f32 = 50176
#define VS_A  50176                               // 6 bufs a 17408: [st][comp]
#define VS_B  154624                              // 2 bufs a 18432: [st]
#define VS_SMEM 191488
#define VA_OFF(st, comp)  (VS_A + (((st) * 3) + (comp)) * 17408)
#define VB_OFF(st)        (VS_B + (st) * 18432)

__global__ void __launch_bounds__(512) vectors_tc16(const float* __restrict__ x,
                                                    float* __restrict__ out) {
    extern __shared__ char vsm[];
    float* Xs = (float*)(vsm + VS_XS);
    const int t = threadIdx.x;
    const int lane = t & 31, warp = t >> 5;
    const int wm = warp & 1, wn = warp >> 1;       // 2 x 8
    const int row0 = blockIdx.x * 64;

    uint32_t sb;
    asm("{ .reg .u64 u; cvta.to.shared.u64 u, %1; cvt.u32.u64 %0, u; }"
        : "=r"(sb) : "l"(vsm));

    for (int i = t; i < 64 * 48; i += 512) {
        int r = i / 48, c4 = (i - r * 48) << 2;
        *(float4*)&Xs[r * 196 + c4] =
            *(const float4*)&x[(size_t)(row0 + r) * XDIM + 128 + c4];
    }
    __syncthreads();

    const int kk2 = lane * 2;
    const int mg = warp * 4;

    auto build_A = [&](int c, int st) {
        char* a0p = vsm + VA_OFF(st, 0);
        char* a1p = vsm + VA_OFF(st, 1);
        char* a2p = vsm + VA_OFF(st, 2);
        const int k0g = c * 128;
#pragma unroll
        for (int g = 0; g < 2; g++) {
            int kk = g * 64 + kk2;
            uint32_t pk = __ldg((const uint32_t*)&g_pa[k0g + kk]);
            int u0 = (pk >> 8) & 255, v0 = pk & 255;
            int u1 = pk >> 24,       v1 = (pk >> 16) & 255;
#pragma unroll
            for (int j = 0; j < 4; j++) {
                int m = mg + j;
                const float* Xr = Xs + m * 196;
                const float* pu = Xr + 3 * u0; const float* pv = Xr + 3 * v0;
                float ax = pu[0], ay = pu[1], az = pu[2];
                float bx = pv[0], by = pv[1], bz = pv[2];
                float c00 = ay * bz - az * by;
                float c01 = az * bx - ax * bz;
                float c02 = ax * by - ay * bx;
                pu = Xr + 3 * u1; pv = Xr + 3 * v1;
                ax = pu[0]; ay = pu[1]; az = pu[2];
                bx = pv[0]; by = pv[1]; bz = pv[2];
                float c10 = ay * bz - az * by;
                float c11 = az * bx - ax * bz;
                float c12 = ax * by - ay * bx;
                int doff = m * (V_AS * 2) + kk * 2;
                *(uint32_t*)(a0p + doff) = pack_f16x2(c00, c10);
                *(uint32_t*)(a1p + doff) = pack_f16x2(c01, c11);
                *(uint32_t*)(a2p + doff) = pack_f16x2(c02, c12);
            }
        }
    };
    // B tile: 128 rows x 64 fp16 = 1024 16B-chunks
    auto fetch_B = [&](int c, int st) {
        const uint32_t bb = sb + VB_OFF(st);
#pragma unroll
        for (int j = 0; j < 2; j++) {
            int i = t + j * 512;
            int r = i >> 3, cc = (i & 7) * 8;
            uint32_t doff = (uint32_t)(r * (V_BS * 2) + cc * 2);
            cp16(bb + doff, g_WVA + (size_t)(c * 128 + r) * NVD + cc);
        }
        asm volatile("cp.async.commit_group;" ::: "memory");
    };

    float acc[2][3][4];
#pragma unroll
    for (int mt = 0; mt < 2; mt++)
#pragma unroll
        for (int cp = 0; cp < 3; cp++)
#pragma unroll
            for (int q = 0; q < 4; q++) acc[mt][cp][q] = 0.0f;

    const uint32_t a_eoff = (uint32_t)((wm * 32 + (lane & 15)) * V_AS +
                                       (lane >> 4) * 8) * 2;
    const uint32_t b_eoff = (uint32_t)((lane & 15) * V_BS + wn * 8) * 2;

    fetch_B(0, 0);
    build_A(0, 0);
    asm volatile("cp.async.wait_group 0;" ::: "memory");
    __syncthreads();

    for (int i = 0; i < NCHV; i++) {
        const int s = i & 1;
        if (i + 1 < NCHV) {
            fetch_B(i + 1, s ^ 1);
            build_A(i + 1, s ^ 1);
        }

#pragma unroll
        for (int ks = 0; ks < 8; ks++) {
            uint32_t b[2];
            uint32_t eo_b = b_eoff + (uint32_t)(ks * 16 * V_BS) * 2;
            ldsm_x2t(b, sb + VB_OFF(s) + eo_b);
#pragma unroll
            for (int cp = 0; cp < 3; cp++) {
#pragma unroll
                for (int mt = 0; mt < 2; mt++) {
                    uint32_t a[4];
                    uint32_t eo = a_eoff + (uint32_t)(mt * 16 * V_AS + ks * 16) * 2;
                    ldsm_x4(a, sb + VA_OFF(s, cp) + eo);
                    mma_f16(acc[mt][cp], a, b);
                }
            }
        }

        if (i + 1 < NCHV) {
            asm volatile("cp.async.wait_group 0;" ::: "memory");
            __syncthreads();
        }
    }

    // epilogue: + v011 from transposed fp16 Z (contiguous reads), gate, store
#pragma unroll
    for (int mt = 0; mt < 2; mt++) {
#pragma unroll
        for (int qp = 0; qp < 2; qp++) {
            int rloc = wm * 32 + mt * 16 + (lane >> 2) + qp * 8;
            int rr = row0 + rloc;
            int cc = wn * 8 + (lane & 3) * 2;
            float v0[3], v1[3];
#pragma unroll
            for (int cp = 0; cp < 3; cp++) {
                v0[cp] = acc[mt][cp][qp * 2];
                v1[cp] = acc[mt][cp][qp * 2 + 1];
            }
            const float* Xr = Xs + rloc * 196;
            const uint4* z0q = (const uint4*)(g_Zh + (size_t)rr * 4096 + cc * 64);
            const uint4* z1q = z0q + 8;
#pragma unroll
            for (int q = 0; q < 8; q++) {
                uint4 za = z0q[q], zb = z1q[q];
                uint32_t wa[4] = {za.x, za.y, za.z, za.w};
                uint32_t wb[4] = {zb.x, zb.y, zb.z, zb.w};
                const float* Xn = Xr + q * 24;
#pragma unroll
                for (int h = 0; h < 4; h++) {
                    float2 z0 = h2f(wa[h]);
                    float2 z1 = h2f(wb[h]);
                    const float* Xp = Xn + h * 6;
                    v0[0] += Xp[0] * z0.x + Xp[3] * z0.y;
                    v0[1] += Xp[1] * z0.x + Xp[4] * z0.y;
                    v0[2] += Xp[2] * z0.x + Xp[5] * z0.y;
                    v1[0] += Xp[0] * z1.x + Xp[3] * z1.y;
                    v1[1] += Xp[1] * z1.x + Xp[4] * z1.y;
                    v1[2] += Xp[2] * z1.x + Xp[5] * z1.y;
                }
            }
            float g0 = g_G[rr * 64 + cc];
            float g1 = g_G[rr * 64 + cc + 1];
            float* orow = out + (size_t)rr * XDIM + 128;
#pragma unroll
            for (int k = 0; k < 3; k++) {
                orow[cc * 3 + k]       = v0[k] * g0;
                orow[(cc + 1) * 3 + k] = v1[k] * g1;
            }
        }
    }
}

// ---------------------------------------------------------------------------
extern "C" void kernel_launch(void* const* d_in, const int* in_sizes, int n_in,
                              void* d_out, int out_size) {
    const float* x = 0;
    const float* w000 = 0;
    const float* w110 = 0;
    const float* w011 = 0;
    const float* w111 = 0;
    for (int i = 0; i < n_in; i++) {
        switch (in_sizes[i]) {
            case BATCH * XDIM:       x    = (const float*)d_in[i]; break;
            case NN0 * NN0 * NSV:    w000 = (const float*)d_in[i]; break;
            case NN1 * NN1 * NSV:    w110 = (const float*)d_in[i]; break;
            case NN0 * NN1 * NVD:    w011 = (const float*)d_in[i]; break;
            case NN1 * NN1 * NVD:    w111 = (const float*)d_in[i]; break;
            default: break;
        }
    }
    if (!x)    x    = (const float*)d_in[0];
    if (!w000) w000 = (const float*)d_in[1];
    if (!w110) w110 = (const float*)d_in[2];
    if (!w011) w011 = (const float*)d_in[3];
    if (!w111) w111 = (const float*)d_in[4];
    float* out = (float*)d_out;

    cudaFuncSetAttribute(scalars_tc16,
                         cudaFuncAttributeMaxDynamicSharedMemorySize, TC_SMEM);
    cudaFuncSetAttribute(g3_tc,
                         cudaFuncAttributeMaxDynamicSharedMemorySize, G3T_SMEM);
    cudaFuncSetAttribute(vectors_tc16,
                         cudaFuncAttributeMaxDynamicSharedMemorySize, VS_SMEM);

    build_pairs<<<(KSC_PAD + 255) / 256, 256>>>();
    build_wsc<<<KSC_PAD, NSV>>>(w000, w110);
    build_wva<<<NPA_PAD, NVD>>>(w111);
    build_w3<<<NN0, 1024>>>(w011);
    g3_tc<<<dim3(BATCH / 64, 4096 / 128), 256, G3T_SMEM>>>(x);
    scalars_tc16<<<BATCH / 64, 512, TC_SMEM>>>(x, out);
    vectors_tc16<<<BATCH / 64, 512, VS_SMEM>>>(x, out);
}